// round 16
// baseline (speedup 1.0000x reference)
#include <cuda_runtime.h>
#include <cuda_fp16.h>
#include <math.h>
#include <stdint.h>

#define B_SZ   4096
#define IN_SZ  4096
#define P_SZ   16
#define E_SZ   256
#define M_SZ   65536
#define N_TOT  768
#define EPS_BN 1e-5
// Q prescale so attention uses raw ex2: exp(score/16) = 2^(score * LOG2E/16)
#define QSCALE 0.09016844005556021f
#define ONES_F16X2 0x3C003C00u

// ---------------------------------------------------------------------------
// Scratch (device globals)
// ---------------------------------------------------------------------------
__device__ __half g_xnb[(size_t)M_SZ * E_SZ];   // normalized x f16 [65536][256]
__device__ __half g_wpk[(size_t)N_TOT * E_SZ];  // packed W f16 [768][256]
__device__ float  g_bias[N_TOT];
__device__ __half g_qkv[(size_t)M_SZ * N_TOT];  // C f16 [m][768] = Q'|K|V
__device__ float  g_a [IN_SZ];
__device__ float  g_b [IN_SZ];
__device__ float4 g_ps4 [32 * 1024];
__device__ float4 g_ps24[32 * 1024];

// ---------------------------------------------------------------------------
// PTX helpers
// ---------------------------------------------------------------------------
__device__ __forceinline__ uint32_t smem_u32(const void* p) {
    uint32_t a;
    asm("{ .reg .u64 t; cvta.to.shared.u64 t, %1; cvt.u32.u64 %0, t; }" : "=r"(a) : "l"(p));
    return a;
}
__device__ __forceinline__ uint32_t ex2_f16x2(uint32_t x) {
    uint32_t y;
    asm("ex2.approx.f16x2 %0, %1;" : "=r"(y) : "r"(x));
    return y;
}
__device__ __forceinline__ uint32_t pack_h2(float lo, float hi) {
    __half2 h = __floats2half2_rn(lo, hi);
    return *(uint32_t*)&h;
}
#define CP16(dst, src) \
    asm volatile("cp.async.cg.shared.global [%0], [%1], 16;" :: "r"(dst), "l"(src))
#define CP_COMMIT() asm volatile("cp.async.commit_group;")
#define CP_WAIT0()  asm volatile("cp.async.wait_group 0;" ::: "memory")
#define LDSM4(r0, r1, r2, r3, addr)                                           \
    asm volatile("ldmatrix.sync.aligned.m8n8.x4.shared.b16 {%0,%1,%2,%3}, [%4];" \
                 : "=r"(r0), "=r"(r1), "=r"(r2), "=r"(r3) : "r"(addr))
#define LDSM4T(r, addr)                                                       \
    asm volatile("ldmatrix.sync.aligned.m8n8.x4.trans.shared.b16 {%0,%1,%2,%3}, [%4];" \
                 : "=r"((r)[0]), "=r"((r)[1]), "=r"((r)[2]), "=r"((r)[3]) : "r"(addr))
#define LDSM2T(r, addr)                                                       \
    asm volatile("ldmatrix.sync.aligned.m8n8.x2.trans.shared.b16 {%0,%1}, [%2];" \
                 : "=r"((r)[0]), "=r"((r)[1]) : "r"(addr))
#define LDSM2(r, addr)                                                        \
    asm volatile("ldmatrix.sync.aligned.m8n8.x2.shared.b16 {%0,%1}, [%2];"    \
                 : "=r"((r)[0]), "=r"((r)[1]) : "r"(addr))
// f16-accumulator MMA: d/c are 2 x f16x2 regs
#define MMAH(c, a, b)                                                         \
    asm volatile("mma.sync.aligned.m16n8k16.row.col.f16.f16.f16.f16 "         \
                 "{%0,%1}, {%2,%3,%4,%5}, {%6,%7}, {%0,%1};"                  \
                 : "+r"((c)[0]), "+r"((c)[1])                                 \
                 : "r"((a)[0]), "r"((a)[1]), "r"((a)[2]), "r"((a)[3]),        \
                   "r"((b)[0]), "r"((b)[1]))
// f16-acc, fresh d, zero c
#define MMAH_DC(d, a, b)                                                      \
    asm volatile("mma.sync.aligned.m16n8k16.row.col.f16.f16.f16.f16 "         \
                 "{%0,%1}, {%2,%3,%4,%5}, {%6,%7}, {%8,%9};"                  \
                 : "=r"((d)[0]), "=r"((d)[1])                                 \
                 : "r"((a)[0]), "r"((a)[1]), "r"((a)[2]), "r"((a)[3]),        \
                   "r"((b)[0]), "r"((b)[1]), "r"(0u), "r"(0u))

// ---------------------------------------------------------------------------
// Kernel 1: BN stats stage 1 (unchanged)
// ---------------------------------------------------------------------------
__global__ __launch_bounds__(256) void k_stats_p(const float* __restrict__ x)
{
    const int c4 = blockIdx.x * 64 + (threadIdx.x & 63);
    const int rg = threadIdx.x >> 6;
    const int r0 = blockIdx.y * 128;

    const float4* x4 = (const float4*)x;
    float4 s  = {0.f, 0.f, 0.f, 0.f};
    float4 s2 = {0.f, 0.f, 0.f, 0.f};
    #pragma unroll 8
    for (int i = 0; i < 32; i++) {
        float4 v = x4[(size_t)(r0 + rg + 4 * i) * 1024 + c4];
        s.x += v.x; s.y += v.y; s.z += v.z; s.w += v.w;
        s2.x = fmaf(v.x, v.x, s2.x); s2.y = fmaf(v.y, v.y, s2.y);
        s2.z = fmaf(v.z, v.z, s2.z); s2.w = fmaf(v.w, v.w, s2.w);
    }

    __shared__ float4 sh[256], sh2[256];
    sh[threadIdx.x] = s;  sh2[threadIdx.x] = s2;
    __syncthreads();
    if (rg == 0) {
        const int t = threadIdx.x;
        float4 a0 = sh[t],       a1 = sh[t + 64],
               a2 = sh[t + 128], a3 = sh[t + 192];
        float4 b0 = sh2[t],       b1 = sh2[t + 64],
               b2 = sh2[t + 128], b3 = sh2[t + 192];
        float4 ts  = {a0.x + a1.x + a2.x + a3.x, a0.y + a1.y + a2.y + a3.y,
                      a0.z + a1.z + a2.z + a3.z, a0.w + a1.w + a2.w + a3.w};
        float4 ts2 = {b0.x + b1.x + b2.x + b3.x, b0.y + b1.y + b2.y + b3.y,
                      b0.z + b1.z + b2.z + b3.z, b0.w + b1.w + b2.w + b3.w};
        g_ps4 [blockIdx.y * 1024 + c4] = ts;
        g_ps24[blockIdx.y * 1024 + c4] = ts2;
    }
}

// ---------------------------------------------------------------------------
// Kernel 2: stats finalize + W pack (f16)
// ---------------------------------------------------------------------------
__global__ __launch_bounds__(256) void k_front2(
    const float* __restrict__ gamma, const float* __restrict__ beta,
    const float* __restrict__ WQ, const float* __restrict__ bQ,
    const float* __restrict__ WK, const float* __restrict__ bK,
    const float* __restrict__ WV, const float* __restrict__ bV)
{
    if (blockIdx.x < 16) {
        const int c = blockIdx.x * 256 + threadIdx.x;
        const float* psf  = (const float*)g_ps4;
        const float* ps2f = (const float*)g_ps24;
        float ts = 0.f, ts2 = 0.f;
        #pragma unroll
        for (int rb = 0; rb < 32; rb++) {
            ts  += psf [rb * 4096 + c];
            ts2 += ps2f[rb * 4096 + c];
        }
        const float mean = ts * (1.0f / B_SZ);
        const float var  = ts2 * (1.0f / B_SZ) - mean * mean;
        const float rstd = rsqrtf(var + (float)EPS_BN);
        const float a    = rstd * gamma[c];
        g_a[c] = a;
        g_b[c] = fmaf(-mean, a, beta[c]);
    } else {
        const int g = (blockIdx.x - 16) * 256 + threadIdx.x;
        const int n = g >> 5;
        const int c = g & 31;
        const int p = n & 255;
        const float* W  = (n < 256) ? WQ : (n < 512) ? WK : WV;
        const float* bs = (n < 256) ? bQ : (n < 512) ? bK : bV;

        const float4* w4 = (const float4*)W;
        const int wi = p * 64 + c * 2;
        float4 w0 = w4[wi], w1 = w4[wi + 1];
        uint4 o;
        o.x = pack_h2(w0.x, w0.y); o.y = pack_h2(w0.z, w0.w);
        o.z = pack_h2(w1.x, w1.y); o.w = pack_h2(w1.z, w1.w);
        ((uint4*)g_wpk)[g] = o;
        if (c == 0) g_bias[n] = bs[p];
    }
}

// ---------------------------------------------------------------------------
// Kernel 3: normalize -> f16 row-major [65536][256]
// ---------------------------------------------------------------------------
__global__ __launch_bounds__(256) void k_normalize_f16(const float* __restrict__ x)
{
    const int g = blockIdx.x * 256 + threadIdx.x;
    const int m = g >> 5;
    const int c = g & 31;

    const float4* x4 = (const float4*)x;
    const float4* a4 = (const float4*)g_a;
    const float4* b4 = (const float4*)g_b;
    const int xi = m * 64 + c * 2;
    const int ai = (m & 15) * 64 + c * 2;
    float4 x0 = x4[xi],  x1 = x4[xi + 1];
    float4 av0 = a4[ai], av1 = a4[ai + 1];
    float4 bv0 = b4[ai], bv1 = b4[ai + 1];

    uint4 o;
    o.x = pack_h2(fmaf(x0.x, av0.x, bv0.x), fmaf(x0.y, av0.y, bv0.y));
    o.y = pack_h2(fmaf(x0.z, av0.z, bv0.z), fmaf(x0.w, av0.w, bv0.w));
    o.z = pack_h2(fmaf(x1.x, av1.x, bv1.x), fmaf(x1.y, av1.y, bv1.y));
    o.w = pack_h2(fmaf(x1.z, av1.z, bv1.z), fmaf(x1.w, av1.w, bv1.w));
    ((uint4*)g_xnb)[g] = o;
}

// ---------------------------------------------------------------------------
// Kernel 4: f16 mma.sync GEMM — f16 accumulator chains per kt (K=64),
//   folded into fp32 masters each kt. Q prescaled by QSCALE.
// ---------------------------------------------------------------------------
__global__ __launch_bounds__(128, 2) void k_gemm_mma()
{
    __shared__ __align__(128) char smA[2 * 128 * 128];
    __shared__ __align__(128) char smB[2 * 64 * 128];
    const uint32_t sA = smem_u32(smA);
    const uint32_t sB = smem_u32(smB);

    const int tid = threadIdx.x;
    const int wid = tid >> 5;
    const int lid = tid & 31;
    const int wm  = wid >> 1;
    const int wn  = wid & 1;
    const int n0  = blockIdx.x * 64;
    const int m0  = blockIdx.y * 128;

    const __half* Ab = g_xnb;
    const __half* Bb = g_wpk;

    auto issue = [&](int kt, int buf) {
        #pragma unroll
        for (int i = 0; i < 8; i++) {
            const int idx = tid + i * 128;
            const int ml = idx >> 3, ch = idx & 7;
            const uint32_t dst = sA + buf * 16384 + ml * 128 + ((ch ^ (ml & 7)) * 16);
            CP16(dst, Ab + (size_t)(m0 + ml) * E_SZ + kt * 64 + ch * 8);
        }
        #pragma unroll
        for (int i = 0; i < 4; i++) {
            const int idx = tid + i * 128;
            const int nl = idx >> 3, ch = idx & 7;
            const uint32_t dst = sB + buf * 8192 + nl * 128 + ((ch ^ (nl & 7)) * 16);
            CP16(dst, Bb + (size_t)(n0 + nl) * E_SZ + kt * 64 + ch * 8);
        }
        CP_COMMIT();
    };

    auto ldfrags = [&](uint32_t aBuf, uint32_t bBuf, int ks,
                       uint32_t a[4][4], uint32_t bf[4][2]) {
        const int kca = ks * 2 + ((lid >> 4) & 1);
        #pragma unroll
        for (int mf = 0; mf < 4; mf++) {
            const int m = wm * 64 + mf * 16 + (lid & 15);
            LDSM4(a[mf][0], a[mf][1], a[mf][2], a[mf][3],
                  aBuf + m * 128 + ((kca ^ (m & 7)) * 16));
        }
        const int kcb = ks * 2 + ((lid >> 3) & 1);
        #pragma unroll
        for (int nf2 = 0; nf2 < 2; nf2++) {
            const int n = wn * 32 + nf2 * 16 + (lid & 7) + ((lid >> 4) ? 8 : 0);
            uint32_t r0, r1, r2, r3;
            LDSM4(r0, r1, r2, r3, bBuf + n * 128 + ((kcb ^ (n & 7)) * 16));
            bf[nf2 * 2][0] = r0;     bf[nf2 * 2][1] = r1;
            bf[nf2 * 2 + 1][0] = r2; bf[nf2 * 2 + 1][1] = r3;
        }
    };

    float acc[4][4][4];
    #pragma unroll
    for (int i = 0; i < 4; i++)
        #pragma unroll
        for (int j = 0; j < 4; j++)
            #pragma unroll
            for (int r = 0; r < 4; r++) acc[i][j][r] = 0.0f;

    uint32_t afr[2][4][4], bfr[2][4][2];
    uint32_t hacc[4][4][2];

    issue(0, 0);

    #pragma unroll
    for (int kt = 0; kt < 4; kt++) {
        if (kt < 3) {
            issue(kt + 1, (kt + 1) & 1);
            asm volatile("cp.async.wait_group 1;" ::: "memory");
        } else {
            CP_WAIT0();
        }
        __syncthreads();

        const uint32_t aBuf = sA + (kt & 1) * 16384;
        const uint32_t bBuf = sB + (kt & 1) * 8192;

        ldfrags(aBuf, bBuf, 0, afr[0], bfr[0]);

        #pragma unroll
        for (int ks = 0; ks < 4; ks++) {
            const int cur = ks & 1;
            if (ks < 3)
                ldfrags(aBuf, bBuf, ks + 1, afr[cur ^ 1], bfr[cur ^ 1]);
            #pragma unroll
            for (int mf = 0; mf < 4; mf++)
                #pragma unroll
                for (int nf = 0; nf < 4; nf++) {
                    if (ks == 0) MMAH_DC(hacc[mf][nf], afr[cur][mf], bfr[cur][nf]);
                    else         MMAH   (hacc[mf][nf], afr[cur][mf], bfr[cur][nf]);
                }
        }
        // fold f16 partials (64-term K slice) into fp32 masters
        #pragma unroll
        for (int mf = 0; mf < 4; mf++)
            #pragma unroll
            for (int nf = 0; nf < 4; nf++) {
                float2 f0 = __half22float2(*(__half2*)&hacc[mf][nf][0]);
                float2 f1 = __half22float2(*(__half2*)&hacc[mf][nf][1]);
                acc[mf][nf][0] += f0.x; acc[mf][nf][1] += f0.y;
                acc[mf][nf][2] += f1.x; acc[mf][nf][3] += f1.y;
            }
        __syncthreads();
    }

    const float qs = (n0 < 256) ? QSCALE : 1.0f;
    const int lr = lid >> 2;
    const int lc = (lid & 3) * 2;
    #pragma unroll
    for (int mf = 0; mf < 4; mf++) {
        const int r0g = m0 + wm * 64 + mf * 16 + lr;
        #pragma unroll
        for (int nf = 0; nf < 4; nf++) {
            const int col = n0 + wn * 32 + nf * 8 + lc;
            const float b0v = g_bias[col];
            const float b1v = g_bias[col + 1];
            uint32_t h0 = pack_h2((acc[mf][nf][0] + b0v) * qs, (acc[mf][nf][1] + b1v) * qs);
            uint32_t h1 = pack_h2((acc[mf][nf][2] + b0v) * qs, (acc[mf][nf][3] + b1v) * qs);
            *(uint32_t*)&g_qkv[(size_t)r0g * N_TOT + col]       = h0;
            *(uint32_t*)&g_qkv[(size_t)(r0g + 8) * N_TOT + col] = h1;
        }
    }
}

// ---------------------------------------------------------------------------
// Kernel 5: tensor-core attention + residual, full f16.
//   S-MMA f16-acc output registers ARE the P-V A-fragment (no cvt), ex2 on
//   them directly. P-V + ones-rowsum in f16-acc, folded to fp32 every 4 its.
// ---------------------------------------------------------------------------
__global__ __launch_bounds__(256, 3) void k_attn_tc(const float* __restrict__ x,
                                                    float* __restrict__ out)
{
    __shared__ __align__(128) __half sT[3 * 16 * 256];   // Q'|K|V
    const uint32_t sb = smem_u32(sT);
    const int b    = blockIdx.x >> 1;
    const int half = blockIdx.x & 1;
    const int tid  = threadIdx.x;
    const int w    = tid >> 5;
    const int l    = tid & 31;

    // load 16 rows x 80 chunks: Q-half (16) + K (32) + V (32)
    const char* src = (const char*)(g_qkv + (size_t)b * 16 * N_TOT);
    #pragma unroll
    for (int i = 0; i < 5; i++) {
        const int idx = tid + i * 256;
        const int p  = idx / 80;
        const int cw = idx % 80;
        int mat, c, srcc;
        if (cw < 16) { mat = 0; c = half * 16 + cw; srcc = c; }
        else {
            const int cw2 = cw - 16;
            mat = 1 + (cw2 >> 5); c = cw2 & 31; srcc = 32 + cw2;
        }
        const uint32_t dst = sb + mat * 8192 + p * 512 + ((c ^ (p & 7)) << 4);
        CP16(dst, src + (size_t)p * 1536 + srcc * 16);
    }
    CP_COMMIT(); CP_WAIT0();
    __syncthreads();

    const uint32_t Qb = sb, Kb = sb + 8192, Vb = sb + 16384;

    const int qg = l >> 3, qi = l & 7;
    const int qp = qi + ((qg & 2) ? 8 : 0);
    const int qc = qg & 1;
    uint32_t qa[4];
    LDSM4T(qa, Qb + qp * 512 + (((half * 16 + w * 2 + qc) ^ (qp & 7)) << 4));

    const int kp = l & 15;
    const uint32_t kbase = Kb + kp * 512;
    const int kxor = kp & 7;
    const int vi = l & 7;
    const int vhalf = (l >> 3) & 1;
    const uint32_t vbase0 = Vb + vi * 512;
    const uint32_t vbase1 = Vb + (8 + vi) * 512;
    const int vxor0 = vi & 7;
    const int vxor1 = (8 + vi) & 7;

    float po[2][4];
    #pragma unroll
    for (int pt = 0; pt < 2; pt++)
        #pragma unroll
        for (int r = 0; r < 4; r++) po[pt][r] = 0.0f;
    float rs[2] = {0.f, 0.f};

    uint32_t poh[2][2] = {{0u, 0u}, {0u, 0u}};   // f16x2 partials
    uint32_t rsh[2]    = {0u, 0u};
    uint32_t bones[2]  = {ONES_F16X2, ONES_F16X2};

    uint32_t kf[2][2][2], vf[2][2][2];
    uint32_t sh16[2][2][2];                       // S f16x2: [stage][tile][2]

    // prologue
    LDSM2T(kf[0][0], kbase + ((0 ^ kxor) << 4));
    LDSM2T(kf[0][1], kbase + ((1 ^ kxor) << 4));
    LDSM2(vf[0][0], vbase0 + ((vhalf ^ vxor0) << 4));
    LDSM2(vf[0][1], vbase1 + ((vhalf ^ vxor1) << 4));
    MMAH_DC(sh16[0][0], qa, kf[0][0]);
    MMAH_DC(sh16[0][1], qa, kf[0][1]);

    #pragma unroll
    for (int fs = 0; fs < 16; fs++) {
        const int cur = fs & 1;
        const int nxt = cur ^ 1;

        if (fs < 15) {
            LDSM2T(kf[nxt][0], kbase + (((2 * fs + 2) ^ kxor) << 4));
            LDSM2T(kf[nxt][1], kbase + (((2 * fs + 3) ^ kxor) << 4));
            const int vc = 2 * fs + 2 + vhalf;
            LDSM2(vf[nxt][0], vbase0 + ((vc ^ vxor0) << 4));
            LDSM2(vf[nxt][1], vbase1 + ((vc ^ vxor1) << 4));
            MMAH_DC(sh16[nxt][0], qa, kf[nxt][0]);
            MMAH_DC(sh16[nxt][1], qa, kf[nxt][1]);
        }

        // S (f16) -> ex2 -> A-fragment directly
        uint32_t pa[4];
        pa[0] = ex2_f16x2(sh16[cur][0][0]);
        pa[1] = ex2_f16x2(sh16[cur][0][1]);
        pa[2] = ex2_f16x2(sh16[cur][1][0]);
        pa[3] = ex2_f16x2(sh16[cur][1][1]);

        MMAH(poh[0], pa, vf[cur][0]);
        MMAH(poh[1], pa, vf[cur][1]);
        MMAH(rsh,    pa, bones);

        if ((fs & 3) == 3) {   // fold f16 partials into fp32 (chains <= 64 terms)
            #pragma unroll
            for (int pt = 0; pt < 2; pt++) {
                float2 f0 = __half22float2(*(__half2*)&poh[pt][0]);
                float2 f1 = __half22float2(*(__half2*)&poh[pt][1]);
                po[pt][0] += f0.x; po[pt][1] += f0.y;
                po[pt][2] += f1.x; po[pt][3] += f1.y;
                poh[pt][0] = 0u; poh[pt][1] = 0u;
            }
            rs[0] += __half22float2(*(__half2*)&rsh[0]).x;
            rs[1] += __half22float2(*(__half2*)&rsh[1]).x;
            rsh[0] = 0u; rsh[1] = 0u;
        }
    }

    // ---- epilogue: divide, residual, store ----
    const int lr  = l >> 2;
    const int lc2 = (l & 3) * 2;
    #pragma unroll
    for (int rh = 0; rh < 2; rh++) {
        const int   e_g = half * 128 + w * 16 + lr + rh * 8;
        const float inv = 1.0f / rs[rh];
        #pragma unroll
        for (int pt = 0; pt < 2; pt++) {
            const size_t idx = (size_t)b * IN_SZ + e_g * 16 + pt * 8 + lc2;
            const float2 xv = *(const float2*)(x + idx);
            float2 o;
            o.x = fmaf(po[pt][rh * 2],     inv, xv.x);
            o.y = fmaf(po[pt][rh * 2 + 1], inv, xv.y);
            *(float2*)(out + idx) = o;
        }
    }
}

// ---------------------------------------------------------------------------
// Entry point (5 launches)
// ---------------------------------------------------------------------------
extern "C" void kernel_launch(void* const* d_in, const int* in_sizes, int n_in,
                              void* d_out, int out_size)
{
    const float* x     = (const float*)d_in[0];
    const float* gamma = (const float*)d_in[1];
    const float* beta  = (const float*)d_in[2];
    const float* WQ    = (const float*)d_in[3];
    const float* bQ    = (const float*)d_in[4];
    const float* WK    = (const float*)d_in[5];
    const float* bK    = (const float*)d_in[6];
    const float* WV    = (const float*)d_in[7];
    const float* bV    = (const float*)d_in[8];
    float* out = (float*)d_out;

    k_stats_p       <<<dim3(16, 32), 256>>>(x);
    k_front2        <<<112, 256>>>(gamma, beta, WQ, bQ, WK, bK, WV, bV);
    k_normalize_f16 <<<8192, 256>>>(x);
    k_gemm_mma      <<<dim3(12, 512), 128>>>();
    k_attn_tc       <<<2 * B_SZ, 256>>>(x, out);
}

// round 17
// speedup vs baseline: 1.0921x; 1.0921x over previous
#include <cuda_runtime.h>
#include <cuda_fp16.h>
#include <math.h>
#include <stdint.h>

#define B_SZ   4096
#define IN_SZ  4096
#define P_SZ   16
#define E_SZ   256
#define M_SZ   65536
#define N_TOT  768
#define EPS_BN 1e-5
#define QSCALE 0.09016844005556021f
#define ONES_F16X2 0x3C003C00u

// ---------------------------------------------------------------------------
// Scratch
// ---------------------------------------------------------------------------
__device__ __half g_xnb[(size_t)M_SZ * E_SZ];
__device__ __half g_wpk[(size_t)N_TOT * E_SZ];
__device__ float  g_bias[N_TOT];
__device__ __half g_qkv[(size_t)M_SZ * N_TOT];
__device__ float  g_a [IN_SZ];
__device__ float  g_b [IN_SZ];
__device__ float4 g_ps4 [32 * 1024];
__device__ float4 g_ps24[32 * 1024];

// ---------------------------------------------------------------------------
// PTX helpers
// ---------------------------------------------------------------------------
__device__ __forceinline__ uint32_t smem_u32(const void* p) {
    uint32_t a;
    asm("{ .reg .u64 t; cvta.to.shared.u64 t, %1; cvt.u32.u64 %0, t; }" : "=r"(a) : "l"(p));
    return a;
}
__device__ __forceinline__ uint32_t ex2_f16x2(uint32_t x) {
    uint32_t y;
    asm("ex2.approx.f16x2 %0, %1;" : "=r"(y) : "r"(x));
    return y;
}
__device__ __forceinline__ uint32_t pack_h2(float lo, float hi) {
    __half2 h = __floats2half2_rn(lo, hi);
    return *(uint32_t*)&h;
}
#define CP16(dst, src) \
    asm volatile("cp.async.cg.shared.global [%0], [%1], 16;" :: "r"(dst), "l"(src))
#define CP_COMMIT() asm volatile("cp.async.commit_group;")
#define CP_WAIT0()  asm volatile("cp.async.wait_group 0;" ::: "memory")
#define LDSM4(r0, r1, r2, r3, addr)                                           \
    asm volatile("ldmatrix.sync.aligned.m8n8.x4.shared.b16 {%0,%1,%2,%3}, [%4];" \
                 : "=r"(r0), "=r"(r1), "=r"(r2), "=r"(r3) : "r"(addr))
#define LDSM4T(r, addr)                                                       \
    asm volatile("ldmatrix.sync.aligned.m8n8.x4.trans.shared.b16 {%0,%1,%2,%3}, [%4];" \
                 : "=r"((r)[0]), "=r"((r)[1]), "=r"((r)[2]), "=r"((r)[3]) : "r"(addr))
#define LDSM2T(r, addr)                                                       \
    asm volatile("ldmatrix.sync.aligned.m8n8.x2.trans.shared.b16 {%0,%1}, [%2];" \
                 : "=r"((r)[0]), "=r"((r)[1]) : "r"(addr))
#define LDSM2(r, addr)                                                        \
    asm volatile("ldmatrix.sync.aligned.m8n8.x2.shared.b16 {%0,%1}, [%2];"    \
                 : "=r"((r)[0]), "=r"((r)[1]) : "r"(addr))
// f32-acc, f16-input MMA
#define MMAF(c, a, b)                                                         \
    asm volatile("mma.sync.aligned.m16n8k16.row.col.f32.f16.f16.f32 "         \
                 "{%0,%1,%2,%3}, {%4,%5,%6,%7}, {%8,%9}, {%0,%1,%2,%3};"      \
                 : "+f"((c)[0]), "+f"((c)[1]), "+f"((c)[2]), "+f"((c)[3])     \
                 : "r"((a)[0]), "r"((a)[1]), "r"((a)[2]), "r"((a)[3]),        \
                   "r"((b)[0]), "r"((b)[1]))
// f16-acc MMA: fresh d, zero c
#define MMAH_DC(d, a, b)                                                      \
    asm volatile("mma.sync.aligned.m16n8k16.row.col.f16.f16.f16.f16 "         \
                 "{%0,%1}, {%2,%3,%4,%5}, {%6,%7}, {%8,%9};"                  \
                 : "=r"((d)[0]), "=r"((d)[1])                                 \
                 : "r"((a)[0]), "r"((a)[1]), "r"((a)[2]), "r"((a)[3]),        \
                   "r"((b)[0]), "r"((b)[1]), "r"(0u), "r"(0u))

// ---------------------------------------------------------------------------
// Kernel 1: BN stats stage 1
// ---------------------------------------------------------------------------
__global__ __launch_bounds__(256) void k_stats_p(const float* __restrict__ x)
{
    const int c4 = blockIdx.x * 64 + (threadIdx.x & 63);
    const int rg = threadIdx.x >> 6;
    const int r0 = blockIdx.y * 128;

    const float4* x4 = (const float4*)x;
    float4 s  = {0.f, 0.f, 0.f, 0.f};
    float4 s2 = {0.f, 0.f, 0.f, 0.f};
    #pragma unroll 8
    for (int i = 0; i < 32; i++) {
        float4 v = x4[(size_t)(r0 + rg + 4 * i) * 1024 + c4];
        s.x += v.x; s.y += v.y; s.z += v.z; s.w += v.w;
        s2.x = fmaf(v.x, v.x, s2.x); s2.y = fmaf(v.y, v.y, s2.y);
        s2.z = fmaf(v.z, v.z, s2.z); s2.w = fmaf(v.w, v.w, s2.w);
    }

    __shared__ float4 sh[256], sh2[256];
    sh[threadIdx.x] = s;  sh2[threadIdx.x] = s2;
    __syncthreads();
    if (rg == 0) {
        const int t = threadIdx.x;
        float4 a0 = sh[t],       a1 = sh[t + 64],
               a2 = sh[t + 128], a3 = sh[t + 192];
        float4 b0 = sh2[t],       b1 = sh2[t + 64],
               b2 = sh2[t + 128], b3 = sh2[t + 192];
        float4 ts  = {a0.x + a1.x + a2.x + a3.x, a0.y + a1.y + a2.y + a3.y,
                      a0.z + a1.z + a2.z + a3.z, a0.w + a1.w + a2.w + a3.w};
        float4 ts2 = {b0.x + b1.x + b2.x + b3.x, b0.y + b1.y + b2.y + b3.y,
                      b0.z + b1.z + b2.z + b3.z, b0.w + b1.w + b2.w + b3.w};
        g_ps4 [blockIdx.y * 1024 + c4] = ts;
        g_ps24[blockIdx.y * 1024 + c4] = ts2;
    }
}

// ---------------------------------------------------------------------------
// Kernel 2: stats finalize + W pack (f16)
// ---------------------------------------------------------------------------
__global__ __launch_bounds__(256) void k_front2(
    const float* __restrict__ gamma, const float* __restrict__ beta,
    const float* __restrict__ WQ, const float* __restrict__ bQ,
    const float* __restrict__ WK, const float* __restrict__ bK,
    const float* __restrict__ WV, const float* __restrict__ bV)
{
    if (blockIdx.x < 16) {
        const int c = blockIdx.x * 256 + threadIdx.x;
        const float* psf  = (const float*)g_ps4;
        const float* ps2f = (const float*)g_ps24;
        float ts = 0.f, ts2 = 0.f;
        #pragma unroll
        for (int rb = 0; rb < 32; rb++) {
            ts  += psf [rb * 4096 + c];
            ts2 += ps2f[rb * 4096 + c];
        }
        const float mean = ts * (1.0f / B_SZ);
        const float var  = ts2 * (1.0f / B_SZ) - mean * mean;
        const float rstd = rsqrtf(var + (float)EPS_BN);
        const float a    = rstd * gamma[c];
        g_a[c] = a;
        g_b[c] = fmaf(-mean, a, beta[c]);
    } else {
        const int g = (blockIdx.x - 16) * 256 + threadIdx.x;
        const int n = g >> 5;
        const int c = g & 31;
        const int p = n & 255;
        const float* W  = (n < 256) ? WQ : (n < 512) ? WK : WV;
        const float* bs = (n < 256) ? bQ : (n < 512) ? bK : bV;

        const float4* w4 = (const float4*)W;
        const int wi = p * 64 + c * 2;
        float4 w0 = w4[wi], w1 = w4[wi + 1];
        uint4 o;
        o.x = pack_h2(w0.x, w0.y); o.y = pack_h2(w0.z, w0.w);
        o.z = pack_h2(w1.x, w1.y); o.w = pack_h2(w1.z, w1.w);
        ((uint4*)g_wpk)[g] = o;
        if (c == 0) g_bias[n] = bs[p];
    }
}

// ---------------------------------------------------------------------------
// Kernel 3: normalize -> f16 row-major
// ---------------------------------------------------------------------------
__global__ __launch_bounds__(256) void k_normalize_f16(const float* __restrict__ x)
{
    const int g = blockIdx.x * 256 + threadIdx.x;
    const int m = g >> 5;
    const int c = g & 31;

    const float4* x4 = (const float4*)x;
    const float4* a4 = (const float4*)g_a;
    const float4* b4 = (const float4*)g_b;
    const int xi = m * 64 + c * 2;
    const int ai = (m & 15) * 64 + c * 2;
    float4 x0 = x4[xi],  x1 = x4[xi + 1];
    float4 av0 = a4[ai], av1 = a4[ai + 1];
    float4 bv0 = b4[ai], bv1 = b4[ai + 1];

    uint4 o;
    o.x = pack_h2(fmaf(x0.x, av0.x, bv0.x), fmaf(x0.y, av0.y, bv0.y));
    o.y = pack_h2(fmaf(x0.z, av0.z, bv0.z), fmaf(x0.w, av0.w, bv0.w));
    o.z = pack_h2(fmaf(x1.x, av1.x, bv1.x), fmaf(x1.y, av1.y, bv1.y));
    o.w = pack_h2(fmaf(x1.z, av1.z, bv1.z), fmaf(x1.w, av1.w, bv1.w));
    ((uint4*)g_xnb)[g] = o;
}

// ---------------------------------------------------------------------------
// Kernel 4: f16-input, f32-acc GEMM (exact r15 structure — at HMMA roofline)
// ---------------------------------------------------------------------------
__global__ __launch_bounds__(128, 3) void k_gemm_mma()
{
    __shared__ __align__(128) char smA[2 * 128 * 128];
    __shared__ __align__(128) char smB[2 * 64 * 128];
    const uint32_t sA = smem_u32(smA);
    const uint32_t sB = smem_u32(smB);

    const int tid = threadIdx.x;
    const int wid = tid >> 5;
    const int lid = tid & 31;
    const int wm  = wid >> 1;
    const int wn  = wid & 1;
    const int n0  = blockIdx.x * 64;
    const int m0  = blockIdx.y * 128;

    const __half* Ab = g_xnb;
    const __half* Bb = g_wpk;

    auto issue = [&](int kt, int buf) {
        #pragma unroll
        for (int i = 0; i < 8; i++) {
            const int idx = tid + i * 128;
            const int ml = idx >> 3, ch = idx & 7;
            const uint32_t dst = sA + buf * 16384 + ml * 128 + ((ch ^ (ml & 7)) * 16);
            CP16(dst, Ab + (size_t)(m0 + ml) * E_SZ + kt * 64 + ch * 8);
        }
        #pragma unroll
        for (int i = 0; i < 4; i++) {
            const int idx = tid + i * 128;
            const int nl = idx >> 3, ch = idx & 7;
            const uint32_t dst = sB + buf * 8192 + nl * 128 + ((ch ^ (nl & 7)) * 16);
            CP16(dst, Bb + (size_t)(n0 + nl) * E_SZ + kt * 64 + ch * 8);
        }
        CP_COMMIT();
    };

    auto ldfrags = [&](uint32_t aBuf, uint32_t bBuf, int ks,
                       uint32_t a[4][4], uint32_t bf[4][2]) {
        const int kca = ks * 2 + ((lid >> 4) & 1);
        #pragma unroll
        for (int mf = 0; mf < 4; mf++) {
            const int m = wm * 64 + mf * 16 + (lid & 15);
            LDSM4(a[mf][0], a[mf][1], a[mf][2], a[mf][3],
                  aBuf + m * 128 + ((kca ^ (m & 7)) * 16));
        }
        const int kcb = ks * 2 + ((lid >> 3) & 1);
        #pragma unroll
        for (int nf2 = 0; nf2 < 2; nf2++) {
            const int n = wn * 32 + nf2 * 16 + (lid & 7) + ((lid >> 4) ? 8 : 0);
            uint32_t r0, r1, r2, r3;
            LDSM4(r0, r1, r2, r3, bBuf + n * 128 + ((kcb ^ (n & 7)) * 16));
            bf[nf2 * 2][0] = r0;     bf[nf2 * 2][1] = r1;
            bf[nf2 * 2 + 1][0] = r2; bf[nf2 * 2 + 1][1] = r3;
        }
    };

    float acc[4][4][4];
    #pragma unroll
    for (int i = 0; i < 4; i++)
        #pragma unroll
        for (int j = 0; j < 4; j++)
            #pragma unroll
            for (int r = 0; r < 4; r++) acc[i][j][r] = 0.0f;

    uint32_t afr[2][4][4], bfr[2][4][2];

    issue(0, 0);

    #pragma unroll
    for (int kt = 0; kt < 4; kt++) {
        if (kt < 3) {
            issue(kt + 1, (kt + 1) & 1);
            asm volatile("cp.async.wait_group 1;" ::: "memory");
        } else {
            CP_WAIT0();
        }
        __syncthreads();

        const uint32_t aBuf = sA + (kt & 1) * 16384;
        const uint32_t bBuf = sB + (kt & 1) * 8192;

        ldfrags(aBuf, bBuf, 0, afr[0], bfr[0]);

        #pragma unroll
        for (int ks = 0; ks < 4; ks++) {
            const int cur = ks & 1;
            if (ks < 3)
                ldfrags(aBuf, bBuf, ks + 1, afr[cur ^ 1], bfr[cur ^ 1]);
            #pragma unroll
            for (int mf = 0; mf < 4; mf++)
                #pragma unroll
                for (int nf = 0; nf < 4; nf++)
                    MMAF(acc[mf][nf], afr[cur][mf], bfr[cur][nf]);
        }
        __syncthreads();
    }

    const float qs = (n0 < 256) ? QSCALE : 1.0f;
    const int lr = lid >> 2;
    const int lc = (lid & 3) * 2;
    #pragma unroll
    for (int mf = 0; mf < 4; mf++) {
        const int r0g = m0 + wm * 64 + mf * 16 + lr;
        #pragma unroll
        for (int nf = 0; nf < 4; nf++) {
            const int col = n0 + wn * 32 + nf * 8 + lc;
            const float b0v = g_bias[col];
            const float b1v = g_bias[col + 1];
            uint32_t h0 = pack_h2((acc[mf][nf][0] + b0v) * qs, (acc[mf][nf][1] + b1v) * qs);
            uint32_t h1 = pack_h2((acc[mf][nf][2] + b0v) * qs, (acc[mf][nf][3] + b1v) * qs);
            *(uint32_t*)&g_qkv[(size_t)r0g * N_TOT + col]       = h0;
            *(uint32_t*)&g_qkv[(size_t)(r0g + 8) * N_TOT + col] = h1;
        }
    }
}

// ---------------------------------------------------------------------------
// Kernel 5: attention + residual.  S-MMA f16-acc -> ex2.f16x2 directly on
//   acc regs (= P·V A-fragment, zero cvts) -> P·V + ones-rowsum in f32-acc
//   (no folds). r15 grid/occupancy (2 CTAs per b, 3 CTAs/SM).
// ---------------------------------------------------------------------------
__global__ __launch_bounds__(256, 3) void k_attn_tc(const float* __restrict__ x,
                                                    float* __restrict__ out)
{
    __shared__ __align__(128) __half sT[3 * 16 * 256];
    const uint32_t sb = smem_u32(sT);
    const int b    = blockIdx.x >> 1;
    const int half = blockIdx.x & 1;
    const int tid  = threadIdx.x;
    const int w    = tid >> 5;
    const int l    = tid & 31;

    // load 16 rows x 80 chunks: Q-half (16) + K (32) + V (32)
    const char* src = (const char*)(g_qkv + (size_t)b * 16 * N_TOT);
    #pragma unroll
    for (int i = 0; i < 5; i++) {
        const int idx = tid + i * 256;
        const int p  = idx / 80;
        const int cw = idx % 80;
        int mat, c, srcc;
        if (cw < 16) { mat = 0; c = half * 16 + cw; srcc = c; }
        else {
            const int cw2 = cw - 16;
            mat = 1 + (cw2 >> 5); c = cw2 & 31; srcc = 32 + cw2;
        }
        const uint32_t dst = sb + mat * 8192 + p * 512 + ((c ^ (p & 7)) << 4);
        CP16(dst, src + (size_t)p * 1536 + srcc * 16);
    }
    CP_COMMIT(); CP_WAIT0();
    __syncthreads();

    const uint32_t Qb = sb, Kb = sb + 8192, Vb = sb + 16384;

    const int qg = l >> 3, qi = l & 7;
    const int qp = qi + ((qg & 2) ? 8 : 0);
    const int qc = qg & 1;
    uint32_t qa[4];
    LDSM4T(qa, Qb + qp * 512 + (((half * 16 + w * 2 + qc) ^ (qp & 7)) << 4));

    const int kp = l & 15;
    const uint32_t kbase = Kb + kp * 512;
    const int kxor = kp & 7;
    const int vi = l & 7;
    const int vhalf = (l >> 3) & 1;
    const uint32_t vbase0 = Vb + vi * 512;
    const uint32_t vbase1 = Vb + (8 + vi) * 512;
    const int vxor0 = vi & 7;
    const int vxor1 = (8 + vi) & 7;

    float po[2][4];
    #pragma unroll
    for (int pt = 0; pt < 2; pt++)
        #pragma unroll
        for (int r = 0; r < 4; r++) po[pt][r] = 0.0f;
    float rsa[4] = {0.f, 0.f, 0.f, 0.f};

    uint32_t bones[2] = {ONES_F16X2, ONES_F16X2};

    uint32_t kf[2][2][2], vf[2][2][2];
    uint32_t sh16[2][2][2];

    // prologue
    LDSM2T(kf[0][0], kbase + ((0 ^ kxor) << 4));
    LDSM2T(kf[0][1], kbase + ((1 ^ kxor) << 4));
    LDSM2(vf[0][0], vbase0 + ((vhalf ^ vxor0) << 4));
    LDSM2(vf[0][1], vbase1 + ((vhalf ^ vxor1) << 4));
    MMAH_DC(sh16[0][0], qa, kf[0][0]);
    MMAH_DC(sh16[0][1], qa, kf[0][1]);

    #pragma unroll
    for (int fs = 0; fs < 16; fs++) {
        const int cur = fs & 1;
        const int nxt = cur ^ 1;

        if (fs < 15) {
            LDSM2T(kf[nxt][0], kbase + (((2 * fs + 2) ^ kxor) << 4));
            LDSM2T(kf[nxt][1], kbase + (((2 * fs + 3) ^ kxor) << 4));
            const int vc = 2 * fs + 2 + vhalf;
            LDSM2(vf[nxt][0], vbase0 + ((vc ^ vxor0) << 4));
            LDSM2(vf[nxt][1], vbase1 + ((vc ^ vxor1) << 4));
            MMAH_DC(sh16[nxt][0], qa, kf[nxt][0]);
            MMAH_DC(sh16[nxt][1], qa, kf[nxt][1]);
        }

        // S (f16 acc regs) -> ex2 -> A-fragment directly, no cvt
        uint32_t pa[4];
        pa[0] = ex2_f16x2(sh16[cur][0][0]);
        pa[1] = ex2_f16x2(sh16[cur][0][1]);
        pa[2] = ex2_f16x2(sh16[cur][1][0]);
        pa[3] = ex2_f16x2(sh16[cur][1][1]);

        MMAF(po[0], pa, vf[cur][0]);
        MMAF(po[1], pa, vf[cur][1]);
        MMAF(rsa,   pa, bones);
    }

    // ---- epilogue: divide, residual, store ----
    const int lr  = l >> 2;
    const int lc2 = (l & 3) * 2;
    #pragma unroll
    for (int rh = 0; rh < 2; rh++) {
        const int   e_g = half * 128 + w * 16 + lr + rh * 8;
        const float inv = 1.0f / rsa[rh * 2];
        #pragma unroll
        for (int pt = 0; pt < 2; pt++) {
            const size_t idx = (size_t)b * IN_SZ + e_g * 16 + pt * 8 + lc2;
            const float2 xv = *(const float2*)(x + idx);
            float2 o;
            o.x = fmaf(po[pt][rh * 2],     inv, xv.x);
            o.y = fmaf(po[pt][rh * 2 + 1], inv, xv.y);
            *(float2*)(out + idx) = o;
        }
    }
}

// ---------------------------------------------------------------------------
// Entry point
// ---------------------------------------------------------------------------
extern "C" void kernel_launch(void* const* d_in, const int* in_sizes, int n_in,
                              void* d_out, int out_size)
{
    const float* x     = (const float*)d_in[0];
    const float* gamma = (const float*)d_in[1];
    const float* beta  = (const float*)d_in[2];
    const float* WQ    = (const float*)d_in[3];
    const float* bQ    = (const float*)d_in[4];
    const float* WK    = (const float*)d_in[5];
    const float* bK    = (const float*)d_in[6];
    const float* WV    = (const float*)d_in[7];
    const float* bV    = (const float*)d_in[8];
    float* out = (float*)d_out;

    k_stats_p       <<<dim3(16, 32), 256>>>(x);
    k_front2        <<<112, 256>>>(gamma, beta, WQ, bQ, WK, bK, WV, bV);
    k_normalize_f16 <<<8192, 256>>>(x);
    k_gemm_mma      <<<dim3(12, 512), 128>>>();
    k_attn_tc       <<<2 * B_SZ, 256>>>(x, out);
}